// round 4
// baseline (speedup 1.0000x reference)
#include <cuda_runtime.h>

#define PI_F 3.14159265358979f

// Scalar folded parameters, precomputed per block by thread 0 into smem.
struct Params {
    float rough;
    float inv_ax2, inv_ay2, ax2, ay2;
    float a2m1;
    float s1, s2, s3, s4;        // 1-sub, 1.25*sub, -0.625*sub, 0.625*sub
    float ka, kb;                // 0.04*(0.25*cc*dr_k), 0.96*(0.25*cc*dr_k)
    float cs[3];                 // c_spec0 / (pi*ax*ay)
    float ics[3];                // (1 - c_spec0) / (pi*ax*ay)
    float shn[3];                // sheen premult
    float dif[3];                // (1-mtl)/pi * cd_lin
};

__device__ __forceinline__ float lerpf(float a, float b, float w) { return a + w * (b - a); }

// Cheap-intrinsic param derivation (keeps register footprint low).
__device__ __forceinline__ void compute_params(Params* sp,
        const float* __restrict__ base_color, const float* __restrict__ metallic,
        const float* __restrict__ subsurface, const float* __restrict__ specular,
        const float* __restrict__ roughness, const float* __restrict__ specular_tint,
        const float* __restrict__ anisotropic, const float* __restrict__ sheen,
        const float* __restrict__ sheen_tint, const float* __restrict__ clear_coat,
        const float* __restrict__ clear_coat_gloss) {
    float mtl = metallic[0];
    float sub = subsurface[0];
    float spec = specular[0];
    float rough = roughness[0];
    float sp_tint = specular_tint[0];
    float aniso = anisotropic[0];
    float sh = sheen[0];
    float sh_tint = sheen_tint[0];
    float cc = clear_coat[0];
    float ccg = clear_coat_gloss[0];

    float cd[3];
    #pragma unroll
    for (int i = 0; i < 3; i++) cd[i] = __powf(base_color[i], 2.2f);
    float lum = 0.3f * cd[0] + 0.6f * cd[1] + 0.1f * cd[2];
    float ct[3];
    #pragma unroll
    for (int i = 0; i < 3; i++)
        ct[i] = (lum > 0.0f) ? cd[i] * __fdividef(1.0f, fmaxf(lum, 1e-20f)) : 0.0f;

    float aspect = __fsqrt_rn(1.0f - aniso * 0.9f);
    float r2 = rough * rough;
    float ax = fmaxf(0.001f, __fdividef(r2, aspect));
    float ay = fmaxf(0.001f, r2 * aspect);
    float inv_piaxay = __fdividef(1.0f, PI_F * ax * ay);

    float a_cc = lerpf(0.1f, 0.001f, ccg);
    float a2 = a_cc * a_cc;
    float a2m1, dr_k;
    if (a_cc >= 1.0f) { a2m1 = 0.0f; dr_k = 1.0f / PI_F; }
    else { a2m1 = a2 - 1.0f; dr_k = __fdividef(a2 - 1.0f, PI_F * __logf(a2)); }
    float ccdrk = 0.25f * cc * dr_k;

    sp->rough = rough;
    sp->inv_ax2 = __fdividef(1.0f, ax * ax);
    sp->inv_ay2 = __fdividef(1.0f, ay * ay);
    sp->ax2 = ax * ax;
    sp->ay2 = ay * ay;
    sp->a2m1 = a2m1;
    sp->s1 = 1.0f - sub;
    sp->s2 = 1.25f * sub;
    sp->s3 = -0.625f * sub;
    sp->s4 = 0.625f * sub;
    sp->ka = 0.04f * ccdrk;
    sp->kb = 0.96f * ccdrk;

    #pragma unroll
    for (int i = 0; i < 3; i++) {
        float c = lerpf(spec * 0.08f * lerpf(1.0f, ct[i], sp_tint), cd[i], mtl);
        sp->cs[i]  = c * inv_piaxay;
        sp->ics[i] = (1.0f - c) * inv_piaxay;
        sp->shn[i] = sh * (1.0f - mtl) * lerpf(1.0f, ct[i], sh_tint);
        sp->dif[i] = (1.0f - mtl) * (1.0f / PI_F) * cd[i];
    }
}

__device__ __forceinline__ void brdf_one(const Params& p,
                                         float lx, float ly, float lz,
                                         float vx, float vy, float vz,
                                         float* o) {
    float hx = lx + vx, hy = ly + vy, hz = lz + vz;
    float inv_h = rsqrtf(hx * hx + hy * hy + hz * hz);
    hx *= inv_h; hy *= inv_h; hz *= inv_h;

    float chl = hx * lx + hy * ly + hz * lz;

    bool valid = (lz >= 0.0f) && (vz >= 0.0f);
    float cnl = valid ? lz : 0.5f;
    float cnv = valid ? vz : 0.5f;

    // schlick: m^5
    float ml = __saturatef(1.0f - cnl);
    float mv = __saturatef(1.0f - cnv);
    float mh = __saturatef(1.0f - chl);
    float ml2 = ml * ml, mv2 = mv * mv, mh2 = mh * mh;
    float fl = ml2 * ml2 * ml;
    float fv = mv2 * mv2 * mv;
    float FH = mh2 * mh2 * mh;

    float c2r = chl * chl * p.rough;
    float fd90m1 = 2.0f * c2r - 0.5f;
    float fd = fmaf(fd90m1, fl, 1.0f) * fmaf(fd90m1, fv, 1.0f);
    float fssm1 = c2r - 1.0f;
    float fss = fmaf(fssm1, fl, 1.0f) * fmaf(fssm1, fv, 1.0f);
    float rc = __fdividef(1.0f, cnl + cnv);

    // dm = fd*(1-sub) + 1.25*sub*fss*rc - 0.625*sub*fss + 0.625*sub
    float dm = fmaf(fss, p.s3, p.s4);
    dm = fmaf(fss * rc, p.s2, dm);
    dm = fmaf(fd, p.s1, dm);

    // Ds denom (pi*ax*ay folded into cs/ics): ds = d^2
    float d = fmaf(hx * hx, p.inv_ax2, fmaf(hy * hy, p.inv_ay2, hz * hz));
    float ds = d * d;

    float sa = fmaf(lx * lx, p.ax2, fmaf(ly * ly, p.ay2, cnl * cnl));
    float As = fmaf(sa, rsqrtf(sa), cnl);
    float sv = fmaf(vx * vx, p.ax2, fmaf(vy * vy, p.ay2, cnv * cnv));
    float Av = fmaf(sv, rsqrtf(sv), cnv);
    float GsDs = __fdividef(1.0f, ds * As * Av);

    // clear coat
    float ga = fmaf(cnl * cnl, 0.9375f, 0.0625f);
    float gb = fmaf(cnv * cnv, 0.9375f, 0.0625f);
    float Br = fmaf(ga, rsqrtf(ga), cnl) * fmaf(gb, rsqrtf(gb), cnv);
    float t = fmaf(p.a2m1, hz * hz, 1.0f);
    float clear = fmaf(FH, p.kb, p.ka) * __fdividef(1.0f, t * Br);

    #pragma unroll
    for (int c = 0; c < 3; c++) {
        float fs = fmaf(FH, p.ics[c], p.cs[c]);
        float r = fmaf(p.dif[c], dm, clear);
        r = fmaf(FH, p.shn[c], r);
        r = fmaf(GsDs, fs, r);
        o[c] = valid ? r : 0.0f;
    }
}

#define SCALAR_ARGS                                                            \
    const float* __restrict__ a_bc,  const float* __restrict__ a_mtl,          \
    const float* __restrict__ a_sub, const float* __restrict__ a_spec,         \
    const float* __restrict__ a_rgh, const float* __restrict__ a_spt,          \
    const float* __restrict__ a_ani, const float* __restrict__ a_shn,          \
    const float* __restrict__ a_sht, const float* __restrict__ a_cc,           \
    const float* __restrict__ a_ccg

#define SCALAR_PASS a_bc, a_mtl, a_sub, a_spec, a_rgh, a_spt, a_ani, a_shn, a_sht, a_cc, a_ccg

// 4 elements/thread via float4 I/O; params in smem; min 6 blocks/SM.
__global__ void __launch_bounds__(256, 6)
brdf_kernel_vec(const float4* __restrict__ in, float4* __restrict__ out,
                int nquad, SCALAR_ARGS) {
    __shared__ Params sp;
    int tid = blockIdx.x * blockDim.x + threadIdx.x;
    bool active = tid < nquad;

    // Bulk loads first — overlap thread-0's param derivation.
    float4 L[6];
    if (active) {
        #pragma unroll
        for (int i = 0; i < 6; i++) L[i] = in[(size_t)tid * 6 + i];
    }

    if (threadIdx.x == 0) compute_params(&sp, SCALAR_PASS);
    __syncthreads();
    if (!active) return;

    float ib[24];
    #pragma unroll
    for (int i = 0; i < 6; i++) {
        ib[4 * i + 0] = L[i].x;
        ib[4 * i + 1] = L[i].y;
        ib[4 * i + 2] = L[i].z;
        ib[4 * i + 3] = L[i].w;
    }

    float ob[12];
    #pragma unroll
    for (int e = 0; e < 4; e++) {
        brdf_one(sp,
                 ib[6 * e + 0], ib[6 * e + 1], ib[6 * e + 2],
                 ib[6 * e + 3], ib[6 * e + 4], ib[6 * e + 5],
                 &ob[3 * e]);
    }

    #pragma unroll
    for (int i = 0; i < 3; i++) {
        float4 o;
        o.x = ob[4 * i + 0];
        o.y = ob[4 * i + 1];
        o.z = ob[4 * i + 2];
        o.w = ob[4 * i + 3];
        out[(size_t)tid * 3 + i] = o;
    }
}

// Scalar tail (elements [start, n)).
__global__ void __launch_bounds__(128)
brdf_kernel_tail(const float* __restrict__ in, float* __restrict__ out,
                 int start, int n, SCALAR_ARGS) {
    __shared__ Params sp;
    if (threadIdx.x == 0) compute_params(&sp, SCALAR_PASS);
    __syncthreads();
    int i = start + blockIdx.x * blockDim.x + threadIdx.x;
    if (i >= n) return;
    const float* q = in + (size_t)i * 6;
    float o[3];
    brdf_one(sp, q[0], q[1], q[2], q[3], q[4], q[5], o);
    out[(size_t)i * 3 + 0] = o[0];
    out[(size_t)i * 3 + 1] = o[1];
    out[(size_t)i * 3 + 2] = o[2];
}

extern "C" void kernel_launch(void* const* d_in, const int* in_sizes, int n_in,
                              void* d_out, int out_size) {
    const float* inputs = (const float*)d_in[0];
    int n = in_sizes[0] / 6;

    const float* a_bc  = (const float*)d_in[1];
    const float* a_mtl = (const float*)d_in[2];
    const float* a_sub = (const float*)d_in[3];
    const float* a_spec= (const float*)d_in[4];
    const float* a_rgh = (const float*)d_in[5];
    const float* a_spt = (const float*)d_in[6];
    const float* a_ani = (const float*)d_in[7];
    const float* a_shn = (const float*)d_in[8];
    const float* a_sht = (const float*)d_in[9];
    const float* a_cc  = (const float*)d_in[10];
    const float* a_ccg = (const float*)d_in[11];

    int nquad = n / 4;
    if (nquad > 0) {
        int threads = 256;
        int blocks = (nquad + threads - 1) / threads;
        brdf_kernel_vec<<<blocks, threads>>>((const float4*)inputs,
                                             (float4*)d_out, nquad,
                                             SCALAR_PASS);
    }
    int rem = n - nquad * 4;
    if (rem > 0) {
        brdf_kernel_tail<<<(rem + 127) / 128, 128>>>(inputs, (float*)d_out,
                                                     nquad * 4, n, SCALAR_PASS);
    }
}

// round 5
// speedup vs baseline: 1.3733x; 1.3733x over previous
#include <cuda_runtime.h>

#define PI_F 3.14159265358979f

// Scalar folded parameters, precomputed per block by thread 0 into smem.
struct Params {
    float rough;
    float inv_ax2, inv_ay2, ax2, ay2;
    float a2m1;
    float s1, s2, s3, s4;        // 1-sub, 1.25*sub, -0.625*sub, 0.625*sub
    float ka, kb;                // 0.04*(0.25*cc*dr_k), 0.96*(0.25*cc*dr_k)
    float cs[3];                 // c_spec0 / (pi*ax*ay)
    float ics[3];                // (1 - c_spec0) / (pi*ax*ay)
    float shn[3];                // sheen premult
    float dif[3];                // (1-mtl)/pi * cd_lin
};

__device__ __forceinline__ float lerpf(float a, float b, float w) { return a + w * (b - a); }

// Intrinsic-only param derivation — short MUFU sequences, minimal registers.
__device__ __forceinline__ void compute_params(Params* sp,
        const float* __restrict__ base_color, const float* __restrict__ metallic,
        const float* __restrict__ subsurface, const float* __restrict__ specular,
        const float* __restrict__ roughness, const float* __restrict__ specular_tint,
        const float* __restrict__ anisotropic, const float* __restrict__ sheen,
        const float* __restrict__ sheen_tint, const float* __restrict__ clear_coat,
        const float* __restrict__ clear_coat_gloss) {
    float mtl = metallic[0];
    float sub = subsurface[0];
    float spec = specular[0];
    float rough = roughness[0];
    float sp_tint = specular_tint[0];
    float aniso = anisotropic[0];
    float sh = sheen[0];
    float sh_tint = sheen_tint[0];
    float cc = clear_coat[0];
    float ccg = clear_coat_gloss[0];

    float cd[3];
    #pragma unroll
    for (int i = 0; i < 3; i++) cd[i] = __powf(base_color[i], 2.2f);
    float lum = 0.3f * cd[0] + 0.6f * cd[1] + 0.1f * cd[2];
    float inv_lum = (lum > 0.0f) ? __fdividef(1.0f, fmaxf(lum, 1e-20f)) : 0.0f;

    float aspect = __fsqrt_rn(1.0f - aniso * 0.9f);
    float r2 = rough * rough;
    float ax = fmaxf(0.001f, __fdividef(r2, aspect));
    float ay = fmaxf(0.001f, r2 * aspect);
    float inv_piaxay = __fdividef(1.0f, PI_F * ax * ay);

    float a_cc = lerpf(0.1f, 0.001f, ccg);
    float a2 = a_cc * a_cc;
    float a2m1, dr_k;
    if (a_cc >= 1.0f) { a2m1 = 0.0f; dr_k = 1.0f / PI_F; }
    else { a2m1 = a2 - 1.0f; dr_k = __fdividef(a2 - 1.0f, PI_F * __logf(a2)); }
    float ccdrk = 0.25f * cc * dr_k;

    sp->rough = rough;
    sp->inv_ax2 = __fdividef(1.0f, ax * ax);
    sp->inv_ay2 = __fdividef(1.0f, ay * ay);
    sp->ax2 = ax * ax;
    sp->ay2 = ay * ay;
    sp->a2m1 = a2m1;
    sp->s1 = 1.0f - sub;
    sp->s2 = 1.25f * sub;
    sp->s3 = -0.625f * sub;
    sp->s4 = 0.625f * sub;
    sp->ka = 0.04f * ccdrk;
    sp->kb = 0.96f * ccdrk;

    #pragma unroll
    for (int i = 0; i < 3; i++) {
        float ct = cd[i] * inv_lum;
        float c = lerpf(spec * 0.08f * lerpf(1.0f, ct, sp_tint), cd[i], mtl);
        sp->cs[i]  = c * inv_piaxay;
        sp->ics[i] = (1.0f - c) * inv_piaxay;
        sp->shn[i] = sh * (1.0f - mtl) * lerpf(1.0f, ct, sh_tint);
        sp->dif[i] = (1.0f - mtl) * (1.0f / PI_F) * cd[i];
    }
}

__device__ __forceinline__ void brdf_one(const Params& p,
                                         float lx, float ly, float lz,
                                         float vx, float vy, float vz,
                                         float* o) {
    float hx = lx + vx, hy = ly + vy, hz = lz + vz;
    float inv_h = rsqrtf(hx * hx + hy * hy + hz * hz);
    hx *= inv_h; hy *= inv_h; hz *= inv_h;

    float chl = hx * lx + hy * ly + hz * lz;

    bool valid = (lz >= 0.0f) && (vz >= 0.0f);
    float cnl = valid ? lz : 0.5f;
    float cnv = valid ? vz : 0.5f;

    // schlick: m^5
    float ml = __saturatef(1.0f - cnl);
    float mv = __saturatef(1.0f - cnv);
    float mh = __saturatef(1.0f - chl);
    float ml2 = ml * ml, mv2 = mv * mv, mh2 = mh * mh;
    float fl = ml2 * ml2 * ml;
    float fv = mv2 * mv2 * mv;
    float FH = mh2 * mh2 * mh;

    float c2r = chl * chl * p.rough;
    float fd90m1 = 2.0f * c2r - 0.5f;
    float fd = fmaf(fd90m1, fl, 1.0f) * fmaf(fd90m1, fv, 1.0f);
    float fssm1 = c2r - 1.0f;
    float fss = fmaf(fssm1, fl, 1.0f) * fmaf(fssm1, fv, 1.0f);
    float rc = __fdividef(1.0f, cnl + cnv);

    // dm = fd*(1-sub) + 1.25*sub*fss*rc - 0.625*sub*fss + 0.625*sub
    float dm = fmaf(fss, p.s3, p.s4);
    dm = fmaf(fss * rc, p.s2, dm);
    dm = fmaf(fd, p.s1, dm);

    // Ds denom (pi*ax*ay folded into cs/ics): ds = d^2
    float d = fmaf(hx * hx, p.inv_ax2, fmaf(hy * hy, p.inv_ay2, hz * hz));
    float ds = d * d;

    float sa = fmaf(lx * lx, p.ax2, fmaf(ly * ly, p.ay2, cnl * cnl));
    float As = fmaf(sa, rsqrtf(sa), cnl);
    float sv = fmaf(vx * vx, p.ax2, fmaf(vy * vy, p.ay2, cnv * cnv));
    float Av = fmaf(sv, rsqrtf(sv), cnv);
    float GsDs = __fdividef(1.0f, ds * As * Av);

    // clear coat
    float ga = fmaf(cnl * cnl, 0.9375f, 0.0625f);
    float gb = fmaf(cnv * cnv, 0.9375f, 0.0625f);
    float Br = fmaf(ga, rsqrtf(ga), cnl) * fmaf(gb, rsqrtf(gb), cnv);
    float t = fmaf(p.a2m1, hz * hz, 1.0f);
    float clear = fmaf(FH, p.kb, p.ka) * __fdividef(1.0f, t * Br);

    #pragma unroll
    for (int c = 0; c < 3; c++) {
        float fs = fmaf(FH, p.ics[c], p.cs[c]);
        float r = fmaf(p.dif[c], dm, clear);
        r = fmaf(FH, p.shn[c], r);
        r = fmaf(GsDs, fs, r);
        o[c] = valid ? r : 0.0f;
    }
}

#define SCALAR_ARGS                                                            \
    const float* __restrict__ a_bc,  const float* __restrict__ a_mtl,          \
    const float* __restrict__ a_sub, const float* __restrict__ a_spec,         \
    const float* __restrict__ a_rgh, const float* __restrict__ a_spt,          \
    const float* __restrict__ a_ani, const float* __restrict__ a_shn,          \
    const float* __restrict__ a_sht, const float* __restrict__ a_cc,           \
    const float* __restrict__ a_ccg

#define SCALAR_PASS a_bc, a_mtl, a_sub, a_spec, a_rgh, a_spt, a_ani, a_shn, a_sht, a_cc, a_ccg

// 4 elements/thread via float4 I/O; params in smem; NO min-blocks cap
// (R4 proved a forced reg cap spills the 36-float working set).
__global__ void __launch_bounds__(256)
brdf_kernel_vec(const float4* __restrict__ in, float4* __restrict__ out,
                int nquad, SCALAR_ARGS) {
    __shared__ Params sp;
    int tid = blockIdx.x * blockDim.x + threadIdx.x;
    bool active = tid < nquad;

    // Bulk loads first — overlap thread-0's param derivation.
    float4 L[6];
    if (active) {
        #pragma unroll
        for (int i = 0; i < 6; i++) L[i] = in[(size_t)tid * 6 + i];
    }

    if (threadIdx.x == 0) compute_params(&sp, SCALAR_PASS);
    __syncthreads();
    if (!active) return;

    float ib[24];
    #pragma unroll
    for (int i = 0; i < 6; i++) {
        ib[4 * i + 0] = L[i].x;
        ib[4 * i + 1] = L[i].y;
        ib[4 * i + 2] = L[i].z;
        ib[4 * i + 3] = L[i].w;
    }

    float ob[12];
    #pragma unroll
    for (int e = 0; e < 4; e++) {
        brdf_one(sp,
                 ib[6 * e + 0], ib[6 * e + 1], ib[6 * e + 2],
                 ib[6 * e + 3], ib[6 * e + 4], ib[6 * e + 5],
                 &ob[3 * e]);
    }

    #pragma unroll
    for (int i = 0; i < 3; i++) {
        float4 o;
        o.x = ob[4 * i + 0];
        o.y = ob[4 * i + 1];
        o.z = ob[4 * i + 2];
        o.w = ob[4 * i + 3];
        out[(size_t)tid * 3 + i] = o;
    }
}

// Scalar tail (elements [start, n)).
__global__ void __launch_bounds__(128)
brdf_kernel_tail(const float* __restrict__ in, float* __restrict__ out,
                 int start, int n, SCALAR_ARGS) {
    __shared__ Params sp;
    if (threadIdx.x == 0) compute_params(&sp, SCALAR_PASS);
    __syncthreads();
    int i = start + blockIdx.x * blockDim.x + threadIdx.x;
    if (i >= n) return;
    const float* q = in + (size_t)i * 6;
    float o[3];
    brdf_one(sp, q[0], q[1], q[2], q[3], q[4], q[5], o);
    out[(size_t)i * 3 + 0] = o[0];
    out[(size_t)i * 3 + 1] = o[1];
    out[(size_t)i * 3 + 2] = o[2];
}

extern "C" void kernel_launch(void* const* d_in, const int* in_sizes, int n_in,
                              void* d_out, int out_size) {
    const float* inputs = (const float*)d_in[0];
    int n = in_sizes[0] / 6;

    const float* a_bc  = (const float*)d_in[1];
    const float* a_mtl = (const float*)d_in[2];
    const float* a_sub = (const float*)d_in[3];
    const float* a_spec= (const float*)d_in[4];
    const float* a_rgh = (const float*)d_in[5];
    const float* a_spt = (const float*)d_in[6];
    const float* a_ani = (const float*)d_in[7];
    const float* a_shn = (const float*)d_in[8];
    const float* a_sht = (const float*)d_in[9];
    const float* a_cc  = (const float*)d_in[10];
    const float* a_ccg = (const float*)d_in[11];

    int nquad = n / 4;
    if (nquad > 0) {
        int threads = 256;
        int blocks = (nquad + threads - 1) / threads;
        brdf_kernel_vec<<<blocks, threads>>>((const float4*)inputs,
                                             (float4*)d_out, nquad,
                                             SCALAR_PASS);
    }
    int rem = n - nquad * 4;
    if (rem > 0) {
        brdf_kernel_tail<<<(rem + 127) / 128, 128>>>(inputs, (float*)d_out,
                                                     nquad * 4, n, SCALAR_PASS);
    }
}

// round 6
// speedup vs baseline: 1.3860x; 1.0092x over previous
#include <cuda_runtime.h>

#define PI_F 3.14159265358979f

// Scalar folded parameters, precomputed per block by thread 0 into smem.
struct Params {
    float rough4;                // 0.25 * roughness (c2r = n2 * rough4)
    float inv_ax2, inv_ay2, ax2, ay2;
    float a2m1;
    float s1, s2, s3, s4;        // 1-sub, 1.25*sub, -0.625*sub, 0.625*sub
    float ka, kb;                // 0.04*(0.25*cc*dr_k), 0.96*(0.25*cc*dr_k)
    float cs[3];                 // c_spec0 / (pi*ax*ay)
    float ics[3];                // (1 - c_spec0) / (pi*ax*ay)
    float shn[3];                // sheen premult
    float dif[3];                // (1-mtl)/pi * cd_lin
};

__device__ __forceinline__ float lerpf(float a, float b, float w) { return a + w * (b - a); }

// Intrinsic-only param derivation — short MUFU sequences, minimal registers.
__device__ __forceinline__ void compute_params(Params* sp,
        const float* __restrict__ base_color, const float* __restrict__ metallic,
        const float* __restrict__ subsurface, const float* __restrict__ specular,
        const float* __restrict__ roughness, const float* __restrict__ specular_tint,
        const float* __restrict__ anisotropic, const float* __restrict__ sheen,
        const float* __restrict__ sheen_tint, const float* __restrict__ clear_coat,
        const float* __restrict__ clear_coat_gloss) {
    float mtl = metallic[0];
    float sub = subsurface[0];
    float spec = specular[0];
    float rough = roughness[0];
    float sp_tint = specular_tint[0];
    float aniso = anisotropic[0];
    float sh = sheen[0];
    float sh_tint = sheen_tint[0];
    float cc = clear_coat[0];
    float ccg = clear_coat_gloss[0];

    float cd[3];
    #pragma unroll
    for (int i = 0; i < 3; i++) cd[i] = __powf(base_color[i], 2.2f);
    float lum = 0.3f * cd[0] + 0.6f * cd[1] + 0.1f * cd[2];
    float inv_lum = (lum > 0.0f) ? __fdividef(1.0f, fmaxf(lum, 1e-20f)) : 0.0f;

    float aspect = __fsqrt_rn(1.0f - aniso * 0.9f);
    float r2 = rough * rough;
    float ax = fmaxf(0.001f, __fdividef(r2, aspect));
    float ay = fmaxf(0.001f, r2 * aspect);
    float inv_piaxay = __fdividef(1.0f, PI_F * ax * ay);

    float a_cc = lerpf(0.1f, 0.001f, ccg);
    float a2 = a_cc * a_cc;
    float a2m1, dr_k;
    if (a_cc >= 1.0f) { a2m1 = 0.0f; dr_k = 1.0f / PI_F; }
    else { a2m1 = a2 - 1.0f; dr_k = __fdividef(a2 - 1.0f, PI_F * __logf(a2)); }
    float ccdrk = 0.25f * cc * dr_k;

    sp->rough4 = 0.25f * rough;
    sp->inv_ax2 = __fdividef(1.0f, ax * ax);
    sp->inv_ay2 = __fdividef(1.0f, ay * ay);
    sp->ax2 = ax * ax;
    sp->ay2 = ay * ay;
    sp->a2m1 = a2m1;
    sp->s1 = 1.0f - sub;
    sp->s2 = 1.25f * sub;
    sp->s3 = -0.625f * sub;
    sp->s4 = 0.625f * sub;
    sp->ka = 0.04f * ccdrk;
    sp->kb = 0.96f * ccdrk;

    #pragma unroll
    for (int i = 0; i < 3; i++) {
        float ct = cd[i] * inv_lum;
        float c = lerpf(spec * 0.08f * lerpf(1.0f, ct, sp_tint), cd[i], mtl);
        sp->cs[i]  = c * inv_piaxay;
        sp->ics[i] = (1.0f - c) * inv_piaxay;
        sp->shn[i] = sh * (1.0f - mtl) * lerpf(1.0f, ct, sh_tint);
        sp->dif[i] = (1.0f - mtl) * (1.0f / PI_F) * cd[i];
    }
}

// BRDF on unnormalized half-vector. Uses identities for unit l, v:
//   cos_hl = |l+v|/2          -> chl = 0.5*n2*rsqrt(n2), chl^2 = n2/4
//   cnh^2  = hz_u^2 / n2
//   Ds-term scaling folded:    GsDs = n2^2 / (du^2 * As * Av * pi*ax*ay)
__device__ __forceinline__ void brdf_one(const Params& p,
                                         float lx, float ly, float lz,
                                         float vx, float vy, float vz,
                                         float* o) {
    float hx = lx + vx, hy = ly + vy, hz = lz + vz;
    float n2 = fmaf(hx, hx, fmaf(hy, hy, hz * hz));
    float invh = rsqrtf(n2);
    float inv_n2 = invh * invh;
    float chl = 0.5f * n2 * invh;

    bool valid = (lz >= 0.0f) && (vz >= 0.0f);
    float cnl = valid ? lz : 0.5f;
    float cnv = valid ? vz : 0.5f;

    // schlick: m^5
    float ml = __saturatef(1.0f - cnl);
    float mv = __saturatef(1.0f - cnv);
    float mh = __saturatef(1.0f - chl);
    float ml2 = ml * ml, mv2 = mv * mv, mh2 = mh * mh;
    float fl = ml2 * ml2 * ml;
    float fv = mv2 * mv2 * mv;
    float FH = mh2 * mh2 * mh;

    float c2r = n2 * p.rough4;                 // = chl^2 * rough, exactly
    float fd90m1 = 2.0f * c2r - 0.5f;
    float fd = fmaf(fd90m1, fl, 1.0f) * fmaf(fd90m1, fv, 1.0f);
    float fssm1 = c2r - 1.0f;
    float fss = fmaf(fssm1, fl, 1.0f) * fmaf(fssm1, fv, 1.0f);
    float rc = __fdividef(1.0f, cnl + cnv);

    // dm = fd*(1-sub) + 1.25*sub*fss*rc - 0.625*sub*fss + 0.625*sub
    float dm = fmaf(fss, p.s3, p.s4);
    dm = fmaf(fss * rc, p.s2, dm);
    dm = fmaf(fd, p.s1, dm);

    // unnormalized microfacet denominator
    float du = fmaf(hx * hx, p.inv_ax2, fmaf(hy * hy, p.inv_ay2, hz * hz));

    float sa = fmaf(lx * lx, p.ax2, fmaf(ly * ly, p.ay2, cnl * cnl));
    float As = fmaf(sa, rsqrtf(sa), cnl);
    float sv = fmaf(vx * vx, p.ax2, fmaf(vy * vy, p.ay2, cnv * cnv));
    float Av = fmaf(sv, rsqrtf(sv), cnv);
    float GsDs = __fdividef(n2 * n2, (du * du) * (As * Av));

    // clear coat (cnh^2 = hz_u^2 / n2)
    float cnh2 = (hz * hz) * inv_n2;
    float ga = fmaf(cnl * cnl, 0.9375f, 0.0625f);
    float gb = fmaf(cnv * cnv, 0.9375f, 0.0625f);
    float Br = fmaf(ga, rsqrtf(ga), cnl) * fmaf(gb, rsqrtf(gb), cnv);
    float t = fmaf(p.a2m1, cnh2, 1.0f);
    float clear = fmaf(FH, p.kb, p.ka) * __fdividef(1.0f, t * Br);

    #pragma unroll
    for (int c = 0; c < 3; c++) {
        float fs = fmaf(FH, p.ics[c], p.cs[c]);
        float r = fmaf(p.dif[c], dm, clear);
        r = fmaf(FH, p.shn[c], r);
        r = fmaf(GsDs, fs, r);
        o[c] = valid ? r : 0.0f;
    }
}

#define SCALAR_ARGS                                                            \
    const float* __restrict__ a_bc,  const float* __restrict__ a_mtl,          \
    const float* __restrict__ a_sub, const float* __restrict__ a_spec,         \
    const float* __restrict__ a_rgh, const float* __restrict__ a_spt,          \
    const float* __restrict__ a_ani, const float* __restrict__ a_shn,          \
    const float* __restrict__ a_sht, const float* __restrict__ a_cc,           \
    const float* __restrict__ a_ccg

#define SCALAR_PASS a_bc, a_mtl, a_sub, a_spec, a_rgh, a_spt, a_ani, a_shn, a_sht, a_cc, a_ccg

// 2 elements/thread: 3 float4 loads (16B-aligned), 3 float2 stores (8B-aligned).
// Small working set -> low natural register count -> high occupancy, no spills.
__global__ void __launch_bounds__(256)
brdf_kernel_vec(const float4* __restrict__ in, float2* __restrict__ out,
                int npair, SCALAR_ARGS) {
    __shared__ Params sp;
    int tid = blockIdx.x * blockDim.x + threadIdx.x;
    bool active = tid < npair;

    // Bulk loads first — overlap thread-0's param derivation.
    float4 L[3];
    if (active) {
        #pragma unroll
        for (int i = 0; i < 3; i++) L[i] = in[(size_t)tid * 3 + i];
    }

    if (threadIdx.x == 0) compute_params(&sp, SCALAR_PASS);
    __syncthreads();
    if (!active) return;

    float ob[6];
    brdf_one(sp, L[0].x, L[0].y, L[0].z, L[0].w, L[1].x, L[1].y, &ob[0]);
    brdf_one(sp, L[1].z, L[1].w, L[2].x, L[2].y, L[2].z, L[2].w, &ob[3]);

    #pragma unroll
    for (int i = 0; i < 3; i++) {
        out[(size_t)tid * 3 + i] = make_float2(ob[2 * i], ob[2 * i + 1]);
    }
}

// Scalar tail (elements [start, n)) — only if n is odd.
__global__ void __launch_bounds__(128)
brdf_kernel_tail(const float* __restrict__ in, float* __restrict__ out,
                 int start, int n, SCALAR_ARGS) {
    __shared__ Params sp;
    if (threadIdx.x == 0) compute_params(&sp, SCALAR_PASS);
    __syncthreads();
    int i = start + blockIdx.x * blockDim.x + threadIdx.x;
    if (i >= n) return;
    const float* q = in + (size_t)i * 6;
    float o[3];
    brdf_one(sp, q[0], q[1], q[2], q[3], q[4], q[5], o);
    out[(size_t)i * 3 + 0] = o[0];
    out[(size_t)i * 3 + 1] = o[1];
    out[(size_t)i * 3 + 2] = o[2];
}

extern "C" void kernel_launch(void* const* d_in, const int* in_sizes, int n_in,
                              void* d_out, int out_size) {
    const float* inputs = (const float*)d_in[0];
    int n = in_sizes[0] / 6;

    const float* a_bc  = (const float*)d_in[1];
    const float* a_mtl = (const float*)d_in[2];
    const float* a_sub = (const float*)d_in[3];
    const float* a_spec= (const float*)d_in[4];
    const float* a_rgh = (const float*)d_in[5];
    const float* a_spt = (const float*)d_in[6];
    const float* a_ani = (const float*)d_in[7];
    const float* a_shn = (const float*)d_in[8];
    const float* a_sht = (const float*)d_in[9];
    const float* a_cc  = (const float*)d_in[10];
    const float* a_ccg = (const float*)d_in[11];

    int npair = n / 2;
    if (npair > 0) {
        int threads = 256;
        int blocks = (npair + threads - 1) / threads;
        brdf_kernel_vec<<<blocks, threads>>>((const float4*)inputs,
                                             (float2*)d_out, npair,
                                             SCALAR_PASS);
    }
    int rem = n - npair * 2;
    if (rem > 0) {
        brdf_kernel_tail<<<1, 128>>>(inputs, (float*)d_out,
                                     npair * 2, n, SCALAR_PASS);
    }
}

// round 7
// speedup vs baseline: 1.4033x; 1.0125x over previous
#include <cuda_runtime.h>

#define PI_F 3.14159265358979f

// Scalar folded parameters, precomputed per block by thread 0 into smem.
struct Params {
    float rough4, rough_half;    // 0.25*rough, 0.5*rough
    float inv_ax2, inv_ay2, ax2, ay2;
    float a2m1;
    float s1, s2, s3, s4;        // 1-sub, 1.25*sub, -0.625*sub, 0.625*sub
    float ka, kb;                // 0.04*(0.25*cc*dr_k), 0.96*(0.25*cc*dr_k)
    float cs[3];                 // c_spec0 / (pi*ax*ay)
    float ics[3];                // (1 - c_spec0) / (pi*ax*ay)
    float shn[3];                // sheen premult
    float dif[3];                // (1-mtl)/pi * cd_lin
};

__device__ __forceinline__ float lerpf(float a, float b, float w) { return a + w * (b - a); }

__device__ __forceinline__ void compute_params(Params* sp,
        const float* __restrict__ base_color, const float* __restrict__ metallic,
        const float* __restrict__ subsurface, const float* __restrict__ specular,
        const float* __restrict__ roughness, const float* __restrict__ specular_tint,
        const float* __restrict__ anisotropic, const float* __restrict__ sheen,
        const float* __restrict__ sheen_tint, const float* __restrict__ clear_coat,
        const float* __restrict__ clear_coat_gloss) {
    float mtl = metallic[0];
    float sub = subsurface[0];
    float spec = specular[0];
    float rough = roughness[0];
    float sp_tint = specular_tint[0];
    float aniso = anisotropic[0];
    float sh = sheen[0];
    float sh_tint = sheen_tint[0];
    float cc = clear_coat[0];
    float ccg = clear_coat_gloss[0];

    float cd[3];
    #pragma unroll
    for (int i = 0; i < 3; i++) cd[i] = __powf(base_color[i], 2.2f);
    float lum = 0.3f * cd[0] + 0.6f * cd[1] + 0.1f * cd[2];
    float inv_lum = (lum > 0.0f) ? __fdividef(1.0f, fmaxf(lum, 1e-20f)) : 0.0f;

    float aspect = __fsqrt_rn(1.0f - aniso * 0.9f);
    float r2 = rough * rough;
    float ax = fmaxf(0.001f, __fdividef(r2, aspect));
    float ay = fmaxf(0.001f, r2 * aspect);
    float inv_piaxay = __fdividef(1.0f, PI_F * ax * ay);

    float a_cc = lerpf(0.1f, 0.001f, ccg);
    float a2 = a_cc * a_cc;
    float a2m1, dr_k;
    if (a_cc >= 1.0f) { a2m1 = 0.0f; dr_k = 1.0f / PI_F; }
    else { a2m1 = a2 - 1.0f; dr_k = __fdividef(a2 - 1.0f, PI_F * __logf(a2)); }
    float ccdrk = 0.25f * cc * dr_k;

    sp->rough4 = 0.25f * rough;
    sp->rough_half = 0.5f * rough;
    sp->inv_ax2 = __fdividef(1.0f, ax * ax);
    sp->inv_ay2 = __fdividef(1.0f, ay * ay);
    sp->ax2 = ax * ax;
    sp->ay2 = ay * ay;
    sp->a2m1 = a2m1;
    sp->s1 = 1.0f - sub;
    sp->s2 = 1.25f * sub;
    sp->s3 = -0.625f * sub;
    sp->s4 = 0.625f * sub;
    sp->ka = 0.04f * ccdrk;
    sp->kb = 0.96f * ccdrk;

    #pragma unroll
    for (int i = 0; i < 3; i++) {
        float ct = cd[i] * inv_lum;
        float c = lerpf(spec * 0.08f * lerpf(1.0f, ct, sp_tint), cd[i], mtl);
        sp->cs[i]  = c * inv_piaxay;
        sp->ics[i] = (1.0f - c) * inv_piaxay;
        sp->shn[i] = sh * (1.0f - mtl) * lerpf(1.0f, ct, sh_tint);
        sp->dif[i] = (1.0f - mtl) * (1.0f / PI_F) * cd[i];
    }
}

// BRDF on unnormalized half-vector (identities for unit l, v):
//   chl = 0.5*n2*rsqrt(n2); chl^2*rough = n2*rough4 exactly
//   cnh^2 = hz_u^2 / n2;   GsDs = n2^2 / (du^2 * As * Av) (pi*ax*ay folded)
__device__ __forceinline__ void brdf_one(const Params& p,
                                         float lx, float ly, float lz,
                                         float vx, float vy, float vz,
                                         float* o) {
    float hx = lx + vx, hy = ly + vy, hz = lz + vz;
    float n2 = fmaf(hx, hx, fmaf(hy, hy, hz * hz));
    float invh = rsqrtf(n2);
    float inv_n2 = invh * invh;
    float chl = 0.5f * n2 * invh;

    bool valid = (lz >= 0.0f) && (vz >= 0.0f);
    float cnl = valid ? lz : 0.5f;
    float cnv = valid ? vz : 0.5f;

    float ml = __saturatef(1.0f - cnl);
    float mv = __saturatef(1.0f - cnv);
    float mh = __saturatef(1.0f - chl);
    float ml2 = ml * ml, mv2 = mv * mv, mh2 = mh * mh;
    float fl = ml2 * ml2 * ml;
    float fv = mv2 * mv2 * mv;
    float FH = mh2 * mh2 * mh;

    float fd90m1 = fmaf(n2, p.rough_half, -0.5f);   // 2*c2r - 0.5
    float fd = fmaf(fd90m1, fl, 1.0f) * fmaf(fd90m1, fv, 1.0f);
    float fssm1 = fmaf(n2, p.rough4, -1.0f);        // c2r - 1
    float fss = fmaf(fssm1, fl, 1.0f) * fmaf(fssm1, fv, 1.0f);
    float rc = __fdividef(1.0f, cnl + cnv);

    float dm = fmaf(fss, p.s3, p.s4);
    dm = fmaf(fss * rc, p.s2, dm);
    dm = fmaf(fd, p.s1, dm);

    float du = fmaf(hx * hx, p.inv_ax2, fmaf(hy * hy, p.inv_ay2, hz * hz));

    float sa = fmaf(lx * lx, p.ax2, fmaf(ly * ly, p.ay2, cnl * cnl));
    float As = fmaf(sa, rsqrtf(sa), cnl);
    float sv = fmaf(vx * vx, p.ax2, fmaf(vy * vy, p.ay2, cnv * cnv));
    float Av = fmaf(sv, rsqrtf(sv), cnv);
    float GsDs = __fdividef(n2 * n2, (du * du) * (As * Av));

    float cnh2 = (hz * hz) * inv_n2;
    float ga = fmaf(cnl * cnl, 0.9375f, 0.0625f);
    float gb = fmaf(cnv * cnv, 0.9375f, 0.0625f);
    float Br = fmaf(ga, rsqrtf(ga), cnl) * fmaf(gb, rsqrtf(gb), cnv);
    float t = fmaf(p.a2m1, cnh2, 1.0f);
    float clear = fmaf(FH, p.kb, p.ka) * __fdividef(1.0f, t * Br);

    #pragma unroll
    for (int c = 0; c < 3; c++) {
        float fs = fmaf(FH, p.ics[c], p.cs[c]);
        float r = fmaf(p.dif[c], dm, clear);
        r = fmaf(FH, p.shn[c], r);
        r = fmaf(GsDs, fs, r);
        o[c] = valid ? r : 0.0f;
    }
}

#define SCALAR_ARGS                                                            \
    const float* __restrict__ a_bc,  const float* __restrict__ a_mtl,          \
    const float* __restrict__ a_sub, const float* __restrict__ a_spec,         \
    const float* __restrict__ a_rgh, const float* __restrict__ a_spt,          \
    const float* __restrict__ a_ani, const float* __restrict__ a_shn,          \
    const float* __restrict__ a_sht, const float* __restrict__ a_cc,           \
    const float* __restrict__ a_ccg

#define SCALAR_PASS a_bc, a_mtl, a_sub, a_spec, a_rgh, a_spt, a_ani, a_shn, a_sht, a_cc, a_ccg

// Persistent grid-stride kernel, 2 elems/iteration, software-pipelined loads:
// the next iteration's 3 LDG.128 are issued before computing the current one.
__global__ void __launch_bounds__(256)
brdf_kernel_vec(const float4* __restrict__ in, float2* __restrict__ out,
                int npair, SCALAR_ARGS) {
    __shared__ Params sp;
    const int stride = gridDim.x * blockDim.x;
    int i = blockIdx.x * blockDim.x + threadIdx.x;
    bool active = i < npair;

    // First iteration's loads before the param barrier (overlap t0's work).
    float4 A0, A1, A2;
    if (active) {
        A0 = in[(size_t)i * 3 + 0];
        A1 = in[(size_t)i * 3 + 1];
        A2 = in[(size_t)i * 3 + 2];
    }

    if (threadIdx.x == 0) compute_params(&sp, SCALAR_PASS);
    __syncthreads();

    #pragma unroll 1
    while (active) {
        int j = i + stride;
        bool nact = j < npair;
        float4 B0, B1, B2;
        if (nact) {                       // prefetch next chunk
            B0 = in[(size_t)j * 3 + 0];
            B1 = in[(size_t)j * 3 + 1];
            B2 = in[(size_t)j * 3 + 2];
        }

        float ob[6];
        brdf_one(sp, A0.x, A0.y, A0.z, A0.w, A1.x, A1.y, &ob[0]);
        brdf_one(sp, A1.z, A1.w, A2.x, A2.y, A2.z, A2.w, &ob[3]);

        out[(size_t)i * 3 + 0] = make_float2(ob[0], ob[1]);
        out[(size_t)i * 3 + 1] = make_float2(ob[2], ob[3]);
        out[(size_t)i * 3 + 2] = make_float2(ob[4], ob[5]);

        active = nact;
        i = j;
        A0 = B0; A1 = B1; A2 = B2;
    }
}

// Scalar tail (elements [start, n)) — only if n is odd.
__global__ void __launch_bounds__(128)
brdf_kernel_tail(const float* __restrict__ in, float* __restrict__ out,
                 int start, int n, SCALAR_ARGS) {
    __shared__ Params sp;
    if (threadIdx.x == 0) compute_params(&sp, SCALAR_PASS);
    __syncthreads();
    int i = start + blockIdx.x * blockDim.x + threadIdx.x;
    if (i >= n) return;
    const float* q = in + (size_t)i * 6;
    float o[3];
    brdf_one(sp, q[0], q[1], q[2], q[3], q[4], q[5], o);
    out[(size_t)i * 3 + 0] = o[0];
    out[(size_t)i * 3 + 1] = o[1];
    out[(size_t)i * 3 + 2] = o[2];
}

extern "C" void kernel_launch(void* const* d_in, const int* in_sizes, int n_in,
                              void* d_out, int out_size) {
    const float* inputs = (const float*)d_in[0];
    int n = in_sizes[0] / 6;

    const float* a_bc  = (const float*)d_in[1];
    const float* a_mtl = (const float*)d_in[2];
    const float* a_sub = (const float*)d_in[3];
    const float* a_spec= (const float*)d_in[4];
    const float* a_rgh = (const float*)d_in[5];
    const float* a_spt = (const float*)d_in[6];
    const float* a_ani = (const float*)d_in[7];
    const float* a_shn = (const float*)d_in[8];
    const float* a_sht = (const float*)d_in[9];
    const float* a_cc  = (const float*)d_in[10];
    const float* a_ccg = (const float*)d_in[11];

    int npair = n / 2;
    if (npair > 0) {
        const int threads = 256;
        int blocks = 152 * 4;                       // GB300: 152 SMs, ~4 blocks/SM
        int needed = (npair + threads - 1) / threads;
        if (blocks > needed) blocks = needed;
        brdf_kernel_vec<<<blocks, threads>>>((const float4*)inputs,
                                             (float2*)d_out, npair,
                                             SCALAR_PASS);
    }
    int rem = n - npair * 2;
    if (rem > 0) {
        brdf_kernel_tail<<<1, 128>>>(inputs, (float*)d_out,
                                     npair * 2, n, SCALAR_PASS);
    }
}